// round 17
// baseline (speedup 1.0000x reference)
#include <cuda_runtime.h>
#include <cuda_fp16.h>
#include <cstdint>

#define HEADS 6
#define HD 32
#define CDIM 192
#define NQ 576
#define DISP 4
#define IMG 256
#define BATCH 4
#define TOK 64
#define NWIN 1024
#define MTOT (BATCH * IMG * IMG)
#define ATT_SCALE 0.17677669529663687f

// scratch (allocation-free rule: __device__ globals)
__device__ __half g_qkv[(size_t)MTOT * NQ];     // ROLLED coords, [m, 576]
__device__ float g_bias[TOK * TOK];
__device__ __half g_wqkv_h[NQ * CDIM];          // fp16 weights (pre-converted)
__device__ __half g_wout_h[CDIM * CDIM];

// ---------------------------------------------------------------------------
// mma.sync / ldmatrix helpers (fp16, fp32 accumulate)
// ---------------------------------------------------------------------------
__device__ __forceinline__ void mma_f16(float* c, const uint32_t* a, const uint32_t* b) {
    asm volatile(
        "mma.sync.aligned.m16n8k16.row.col.f32.f16.f16.f32 "
        "{%0,%1,%2,%3}, {%4,%5,%6,%7}, {%8,%9}, {%0,%1,%2,%3};"
        : "+f"(c[0]), "+f"(c[1]), "+f"(c[2]), "+f"(c[3])
        : "r"(a[0]), "r"(a[1]), "r"(a[2]), "r"(a[3]), "r"(b[0]), "r"(b[1]));
}
__device__ __forceinline__ uint32_t smem_u32(const void* p) {
    uint32_t a;
    asm("{ .reg .u64 t; cvta.to.shared.u64 t, %1; cvt.u32.u64 %0, t; }" : "=r"(a) : "l"(p));
    return a;
}
__device__ __forceinline__ void ldsm_x4(uint32_t* r, uint32_t addr) {
    asm volatile("ldmatrix.sync.aligned.m8n8.x4.shared.b16 {%0,%1,%2,%3}, [%4];"
                 : "=r"(r[0]), "=r"(r[1]), "=r"(r[2]), "=r"(r[3]) : "r"(addr));
}
__device__ __forceinline__ void ldsm_x4_t(uint32_t* r, uint32_t addr) {
    asm volatile("ldmatrix.sync.aligned.m8n8.x4.trans.shared.b16 {%0,%1,%2,%3}, [%4];"
                 : "=r"(r[0]), "=r"(r[1]), "=r"(r[2]), "=r"(r[3]) : "r"(addr));
}
__device__ __forceinline__ uint32_t packh2(float a, float b) {
    __half2 h = __floats2half2_rn(a, b);
    return *reinterpret_cast<uint32_t*>(&h);
}

// GEMM smem: BM=64 rows A + 64 rows B, 200 halves/row (400B ≡ 16 mod 128 -> ldsm conflict-free)
#define AST2 200
#define A_H (64 * AST2)
#define SMEM_BYTES (2 * A_H * 2)   // 51200 B

// ---------------------------------------------------------------------------
// Kernel 0a: gather rel-pos bias table;  0b: weights fp32 -> fp16
// ---------------------------------------------------------------------------
__global__ void bias_kernel(const float* __restrict__ pos) {
    int idx = blockIdx.x * blockDim.x + threadIdx.x;
    if (idx < TOK * TOK) {
        int i = idx >> 6, j = idx & 63;
        g_bias[idx] = pos[((i >> 3) - (j >> 3) + 7) * 15 + ((i & 7) - (j & 7) + 7)];
    }
}
__global__ void wconv_kernel(const float* __restrict__ wqkv, const float* __restrict__ wout) {
    int idx = blockIdx.x * blockDim.x + threadIdx.x;
    if (idx < NQ * CDIM)   g_wqkv_h[idx] = __float2half_rn(wqkv[idx]);
    if (idx < CDIM * CDIM) g_wout_h[idx] = __float2half_rn(wout[idx]);
}

// ---------------------------------------------------------------------------
// Kernel 1: QKV GEMM (fp16 m16n8k16). BM=64, 128 thr, warp tile 32x32.
// (unchanged from round 16)
// ---------------------------------------------------------------------------
__global__ __launch_bounds__(128, 4) void qkv_tc(const float* __restrict__ x) {
    extern __shared__ __half smh[];
    __half* As = smh;
    __half* Bsh = smh + A_H;
    uint32_t sbase = smem_u32(smh);
    uint32_t bbase = sbase + A_H * 2;

    int tid = threadIdx.x;
    int wid = tid >> 5, lane = tid & 31;
    int warp_m = (wid >> 1) * 32;
    int warp_n = (wid & 1) * 32;
    int lr = lane >> 2, lc = lane & 3;
    int m0 = blockIdx.x * 64;

    uint32_t aoff0 = sbase + (uint32_t)((warp_m + (lane & 7) + ((lane >> 3) & 1) * 8) * (AST2 * 2)
                                        + ((lane >> 4) & 1) * 16);
    uint32_t aoff1 = aoff0 + 16 * (AST2 * 2);
    uint32_t boff0 = bbase + (uint32_t)((warp_n + (lane & 7) + ((lane >> 4) & 1) * 8) * (AST2 * 2)
                                        + ((lane >> 3) & 1) * 16);
    uint32_t boff1 = boff0 + 16 * (AST2 * 2);

    #pragma unroll
    for (int j = 0; j < 24; j++) {
        int i = tid + j * 128;
        int r = i / 48, c4 = i % 48;
        int m = m0 + r;
        int bb = m >> 16, y = (m >> 8) & 255, xx = m & 255;
        int ys = (y + DISP) & 255, xs = (xx + DISP) & 255;
        float4 v = *(const float4*)(x + ((size_t)((bb * IMG + ys) * IMG + xs)) * CDIM + c4 * 4);
        *(__half2*)&As[r * AST2 + c4 * 4]     = __floats2half2_rn(v.x, v.y);
        *(__half2*)&As[r * AST2 + c4 * 4 + 2] = __floats2half2_rn(v.z, v.w);
    }

    for (int t = 0; t < 9; t++) {
        int n0 = t * 64;
        __syncthreads();
        #pragma unroll
        for (int j = 0; j < 12; j++) {
            int i = tid + j * 128;
            int r = i / 24, c = i % 24;
            *(uint4*)&Bsh[r * AST2 + c * 8] =
                *(const uint4*)(g_wqkv_h + (size_t)(n0 + r) * CDIM + c * 8);
        }
        __syncthreads();

        float acc[2][4][4] = {};
        #pragma unroll
        for (int kk = 0; kk < 12; kk++) {
            uint32_t kb = (uint32_t)(kk * 32);
            uint32_t a0[4], a1[4], b0[4], b1[4];
            ldsm_x4(a0, aoff0 + kb);
            ldsm_x4(a1, aoff1 + kb);
            ldsm_x4(b0, boff0 + kb);
            ldsm_x4(b1, boff1 + kb);
            mma_f16(acc[0][0], a0, b0);     mma_f16(acc[0][1], a0, b0 + 2);
            mma_f16(acc[0][2], a0, b1);     mma_f16(acc[0][3], a0, b1 + 2);
            mma_f16(acc[1][0], a1, b0);     mma_f16(acc[1][1], a1, b0 + 2);
            mma_f16(acc[1][2], a1, b1);     mma_f16(acc[1][3], a1, b1 + 2);
        }

        #pragma unroll
        for (int mt = 0; mt < 2; mt++) {
            size_t r0 = (size_t)(m0 + warp_m + mt * 16 + lr) * NQ + n0 + warp_n;
            size_t r1 = r0 + 8 * NQ;
            #pragma unroll
            for (int nt = 0; nt < 4; nt++) {
                int col = nt * 8 + lc * 2;
                *(__half2*)(g_qkv + r0 + col) = __floats2half2_rn(acc[mt][nt][0], acc[mt][nt][1]);
                *(__half2*)(g_qkv + r1 + col) = __floats2half2_rn(acc[mt][nt][2], acc[mt][nt][3]);
            }
        }
    }
}

// ---------------------------------------------------------------------------
// Kernel 2: FUSED attention + output projection. Block = (b, win), 768 thr
// (24 warps = 6 heads x 4 row-warps). Gather = contiguous 1152B token rows.
// After attention, Q/K/V smem is overlaid with wout; 24 warps then compute
// out[64,192] = O @ wout^T + bout with roll-back store.
// smem: qkv 92160 B | bias 17408 B | O 25600 B = 135168 B -> 1 CTA/SM.
// ---------------------------------------------------------------------------
#define QST2 40    // Q/K/V row stride (halves): 80B
#define OST 200    // O / wout row stride (halves): 400B ≡ 16 mod 128
#define BST 68     // bias row stride (fp32 words)
#define QKV_H (HEADS * 3 * 64 * QST2)                 // 46080 halves = 92160 B
#define BIAS_OFF (QKV_H * 2)                          // byte offset of bias
#define O_OFF (BIAS_OFF + 64 * BST * 4)               // byte offset of O = 109568
#define FUSED_SMEM (O_OFF + 64 * OST * 2)             // 135168 B

__global__ __launch_bounds__(768, 1) void attn_fused(const float* __restrict__ bout,
                                                     float* __restrict__ out) {
    extern __shared__ __half ash[];
    float* bsm = (float*)((char*)ash + BIAS_OFF);
    __half* Osm = (__half*)((char*)ash + O_OFF);

    int bid = blockIdx.x;
    int win = bid & (NWIN - 1);
    int bb = bid >> 10;
    int wy = win >> 5, wx = win & 31;

    int tid = threadIdx.x;
    int wid = tid >> 5, lane = tid & 31;
    int lr = lane >> 2, lc = lane & 3;
    int head = wid >> 2;            // 0..5
    int r_base = (wid & 3) * 16;    // q-row block within head

    // ---- gather Q,K,V all 6 heads: full contiguous token rows ----
    // 64 tokens x 72 16B-chunks = 4608 / 768 thr = 6 contiguous per thread.
    {
        int j = tid / 12;            // token
        int cb = (tid % 12) * 6;     // first chunk
        int y = wy * 8 + (j >> 3), xx = wx * 8 + (j & 7);
        const __half* src = g_qkv + ((size_t)((bb * IMG + y) * IMG + xx)) * NQ;
        #pragma unroll
        for (int l = 0; l < 6; l++) {
            int c8 = (cb + l) * 8;              // half offset within token row
            int tensor = c8 / CDIM;
            int rem = c8 - tensor * CDIM;
            int hh = rem >> 5;
            int cc = rem & 31;
            *(uint4*)&ash[((hh * 3 + tensor) * 64 + j) * QST2 + cc] =
                *(const uint4*)(src + c8);
        }
    }
    // ---- bias staged once per block ----
    #pragma unroll
    for (int l = 0; l < 2; l++) {
        int idx = tid + l * 768;
        if (idx < 1024) {
            int w0 = idx * 4;
            int row = w0 >> 6, col = w0 & 63;
            *(float4*)(bsm + row * BST + col) = *(const float4*)(g_bias + w0);
        }
    }
    __syncthreads();

    uint32_t hb = smem_u32(ash) + (uint32_t)(head * 3 * 64 * QST2 * 2);
    uint32_t qbase = hb;
    uint32_t kbase = hb + 64 * QST2 * 2;
    uint32_t vbase = kbase + 64 * QST2 * 2;

    // ---- S = Q K^T * scale + bias ----
    uint32_t qoff = qbase + (uint32_t)((r_base + (lane & 7) + ((lane >> 3) & 1) * 8) * (QST2 * 2)
                                       + ((lane >> 4) & 1) * 16);
    uint32_t qa[2][4];
    ldsm_x4(qa[0], qoff);
    ldsm_x4(qa[1], qoff + 32);

    float s[8][4] = {};
    #pragma unroll
    for (int p = 0; p < 4; p++) {
        uint32_t koff = kbase + (uint32_t)((p * 16 + (lane & 7) + ((lane >> 4) & 1) * 8) * (QST2 * 2)
                                           + ((lane >> 3) & 1) * 16);
        #pragma unroll
        for (int kk = 0; kk < 2; kk++) {
            uint32_t kb[4];
            ldsm_x4(kb, koff + kk * 32);
            mma_f16(s[2 * p],     qa[kk], kb);
            mma_f16(s[2 * p + 1], qa[kk], kb + 2);
        }
    }

    int row0 = r_base + lr, row1 = r_base + lr + 8;
    #pragma unroll
    for (int nt = 0; nt < 8; nt++) {
        int col = nt * 8 + lc * 2;
        float2 b0 = *(const float2*)(bsm + row0 * BST + col);
        float2 b1 = *(const float2*)(bsm + row1 * BST + col);
        s[nt][0] = s[nt][0] * ATT_SCALE + b0.x;
        s[nt][1] = s[nt][1] * ATT_SCALE + b0.y;
        s[nt][2] = s[nt][2] * ATT_SCALE + b1.x;
        s[nt][3] = s[nt][3] * ATT_SCALE + b1.y;
    }

    // ---- softmax ----
    float mx0 = -1e30f, mx1 = -1e30f;
    #pragma unroll
    for (int nt = 0; nt < 8; nt++) {
        mx0 = fmaxf(mx0, fmaxf(s[nt][0], s[nt][1]));
        mx1 = fmaxf(mx1, fmaxf(s[nt][2], s[nt][3]));
    }
    mx0 = fmaxf(mx0, __shfl_xor_sync(0xffffffff, mx0, 1));
    mx0 = fmaxf(mx0, __shfl_xor_sync(0xffffffff, mx0, 2));
    mx1 = fmaxf(mx1, __shfl_xor_sync(0xffffffff, mx1, 1));
    mx1 = fmaxf(mx1, __shfl_xor_sync(0xffffffff, mx1, 2));
    float sum0 = 0.f, sum1 = 0.f;
    #pragma unroll
    for (int nt = 0; nt < 8; nt++) {
        s[nt][0] = __expf(s[nt][0] - mx0); sum0 += s[nt][0];
        s[nt][1] = __expf(s[nt][1] - mx0); sum0 += s[nt][1];
        s[nt][2] = __expf(s[nt][2] - mx1); sum1 += s[nt][2];
        s[nt][3] = __expf(s[nt][3] - mx1); sum1 += s[nt][3];
    }
    sum0 += __shfl_xor_sync(0xffffffff, sum0, 1);
    sum0 += __shfl_xor_sync(0xffffffff, sum0, 2);
    sum1 += __shfl_xor_sync(0xffffffff, sum1, 1);
    sum1 += __shfl_xor_sync(0xffffffff, sum1, 2);
    float inv0 = 1.f / sum0, inv1 = 1.f / sum1;

    // ---- O = P V (in-register P) ----
    float o[4][4] = {};
    #pragma unroll
    for (int kk = 0; kk < 4; kk++) {
        uint32_t pa[4];
        pa[0] = packh2(s[2 * kk][0],     s[2 * kk][1]);
        pa[1] = packh2(s[2 * kk][2],     s[2 * kk][3]);
        pa[2] = packh2(s[2 * kk + 1][0], s[2 * kk + 1][1]);
        pa[3] = packh2(s[2 * kk + 1][2], s[2 * kk + 1][3]);
        #pragma unroll
        for (int q = 0; q < 2; q++) {
            uint32_t voff = vbase + (uint32_t)((kk * 16 + (lane & 7) + ((lane >> 3) & 1) * 8) * (QST2 * 2)
                                               + (q * 16 + ((lane >> 4) & 1) * 8) * 2);
            uint32_t vb[4];
            ldsm_x4_t(vb, voff);
            mma_f16(o[2 * q],     pa, vb);
            mma_f16(o[2 * q + 1], pa, vb + 2);
        }
    }

    // ---- write O (scaled) to smem [64 tok][OST], cols head*32.. ----
    #pragma unroll
    for (int nt = 0; nt < 4; nt++) {
        int col = head * HD + nt * 8 + lc * 2;
        *(__half2*)&Osm[row0 * OST + col] = __floats2half2_rn(o[nt][0] * inv0, o[nt][1] * inv0);
        *(__half2*)&Osm[row1 * OST + col] = __floats2half2_rn(o[nt][2] * inv1, o[nt][3] * inv1);
    }
    __syncthreads();   // all O written; all V reads done

    // ---- overlay wout (192x192 fp16, stride OST) over dead Q/K/V region ----
    #pragma unroll
    for (int l = 0; l < 6; l++) {
        int i = tid + l * 768;      // 4608 = 192 rows x 24 chunks
        int r = i / 24, c = i % 24;
        *(uint4*)&ash[r * OST + c * 8] = *(const uint4*)(g_wout_h + (size_t)r * CDIM + c * 8);
    }
    __syncthreads();

    // ---- out = O @ wout^T + bout ; 24 warps = 4m x 6n, warp tile 16x32 ----
    int mg = wid & 3, ng = wid >> 2;
    uint32_t obase = smem_u32(ash) + O_OFF;
    uint32_t wbase = smem_u32(ash);
    uint32_t aoff = obase + (uint32_t)((mg * 16 + (lane & 7) + ((lane >> 3) & 1) * 8) * (OST * 2)
                                       + ((lane >> 4) & 1) * 16);
    uint32_t boff0 = wbase + (uint32_t)((ng * 32 + (lane & 7) + ((lane >> 4) & 1) * 8) * (OST * 2)
                                        + ((lane >> 3) & 1) * 16);
    uint32_t boff1 = boff0 + 16 * (OST * 2);

    float acc[4][4] = {};
    #pragma unroll
    for (int kk = 0; kk < 12; kk++) {
        uint32_t kb = (uint32_t)(kk * 32);
        uint32_t a[4], b0[4], b1[4];
        ldsm_x4(a, aoff + kb);
        ldsm_x4(b0, boff0 + kb);
        ldsm_x4(b1, boff1 + kb);
        mma_f16(acc[0], a, b0);  mma_f16(acc[1], a, b0 + 2);
        mma_f16(acc[2], a, b1);  mma_f16(acc[3], a, b1 + 2);
    }

    // ---- epilogue: bias + roll-back store (fp32) ----
    #pragma unroll
    for (int half = 0; half < 2; half++) {
        int token = mg * 16 + lr + half * 8;
        int y = wy * 8 + (token >> 3), xx = wx * 8 + (token & 7);
        int yf = (y + DISP) & 255, xf = (xx + DISP) & 255;
        float* op = out + ((size_t)((bb * IMG + yf) * IMG + xf)) * CDIM + ng * 32;
        #pragma unroll
        for (int nt = 0; nt < 4; nt++) {
            int col = nt * 8 + lc * 2;
            float2 bo = *(const float2*)(bout + ng * 32 + col);
            *(float2*)(op + col) = make_float2(acc[nt][half * 2] + bo.x,
                                               acc[nt][half * 2 + 1] + bo.y);
        }
    }
}

// ---------------------------------------------------------------------------
extern "C" void kernel_launch(void* const* d_in, const int* in_sizes, int n_in,
                              void* d_out, int out_size) {
    const float* x    = (const float*)d_in[0];
    const float* wqkv = (const float*)d_in[1];
    const float* pos  = (const float*)d_in[2];
    const float* wout = (const float*)d_in[3];
    const float* bout = (const float*)d_in[4];
    float* out = (float*)d_out;

    cudaFuncSetAttribute(qkv_tc, cudaFuncAttributeMaxDynamicSharedMemorySize, SMEM_BYTES);
    cudaFuncSetAttribute(attn_fused, cudaFuncAttributeMaxDynamicSharedMemorySize, FUSED_SMEM);

    bias_kernel<<<16, 256>>>(pos);
    wconv_kernel<<<(NQ * CDIM + 255) / 256, 256>>>(wqkv, wout);
    qkv_tc<<<MTOT / 64, 128, SMEM_BYTES>>>(x);
    attn_fused<<<BATCH * NWIN, 768, FUSED_SMEM>>>(bout, out);
}